// round 4
// baseline (speedup 1.0000x reference)
#include <cuda_runtime.h>
#include <cstdint>

#define MARGIN 0.1f
#define TPB 256
#define VPT 2           // float4 vectors per thread: TPB*VPT*4 = 2048 = L
#define EPT (VPT * 4)

// Global accumulators. Zero-initialized at module load; the last CTA of every
// launch resets them to zero after producing the output, so every invocation
// (correctness call, capture call, each graph replay) sees identical state.
__device__ float        g_total;
__device__ float        g_count;
__device__ unsigned int g_done;

__global__ void __launch_bounds__(TPB) hinge_row_kernel(
    const float* __restrict__ scores,
    const int* __restrict__ lens,
    const int* __restrict__ labels,
    int L,
    float* __restrict__ out)
{
    const int row = blockIdx.x;
    const int len = lens[row];
    const size_t base = (size_t)row * (size_t)L;
    const float4* __restrict__ srow = (const float4*)(scores + base);
    const int4*   __restrict__ lrow = (const int4*)(labels + base);
    const int t = threadIdx.x;
    const int L4 = L >> 2;

    float s[EPT];
    bool isNeg[EPT];

    float pos_sum = 0.0f;
    int pos_cnt = 0;

#pragma unroll
    for (int k = 0; k < VPT; k++) {
        const int v = t + k * TPB;
        float4 sv = make_float4(0.f, 0.f, 0.f, 0.f);
        int4   lv = make_int4(-1, -1, -1, -1);
        if (v < L4) {
            sv = __ldcs(&srow[v]);      // streaming: read-once data, evict first
            lv = __ldcs(&lrow[v]);
        }
        const int j0 = v << 2;
        const float se[4] = { sv.x, sv.y, sv.z, sv.w };
        const int   le[4] = { lv.x, lv.y, lv.z, lv.w };
#pragma unroll
        for (int e = 0; e < 4; e++) {
            const int j = j0 + e;
            const bool valid = (j < L) && (j < len);
            const bool p = valid && (le[e] == 1);
            const bool n = valid && (le[e] == 0);
            s[k * 4 + e] = se[e];
            isNeg[k * 4 + e] = n;
            if (p) { pos_sum += se[e]; pos_cnt++; }
        }
    }

    // ---- block reduce pos_sum / pos_cnt ----
    __shared__ float sh_f[TPB / 32];
    __shared__ int   sh_i[TPB / 32];
    __shared__ float sh_chosen;

#pragma unroll
    for (int o = 16; o > 0; o >>= 1) {
        pos_sum += __shfl_down_sync(0xFFFFFFFFu, pos_sum, o);
        pos_cnt += __shfl_down_sync(0xFFFFFFFFu, pos_cnt, o);
    }
    const int wid = t >> 5, lid = t & 31;
    if (lid == 0) { sh_f[wid] = pos_sum; sh_i[wid] = pos_cnt; }
    __syncthreads();
    if (t == 0) {
        float ps = 0.0f; int pc = 0;
#pragma unroll
        for (int w = 0; w < TPB / 32; w++) { ps += sh_f[w]; pc += sh_i[w]; }
        sh_chosen = (pc > 0) ? ps : -MARGIN;
    }
    __syncthreads();
    const float chosen = sh_chosen;

    // ---- hinge over negatives, from register-resident scores ----
    float hs = 0.0f;
    int nc = 0;
#pragma unroll
    for (int k = 0; k < EPT; k++) {
        if (isNeg[k]) {
            hs += fmaxf(MARGIN + s[k] - chosen, 0.0f);
            nc++;
        }
    }
#pragma unroll
    for (int o = 16; o > 0; o >>= 1) {
        hs += __shfl_down_sync(0xFFFFFFFFu, hs, o);
        nc += __shfl_down_sync(0xFFFFFFFFu, nc, o);
    }
    __syncthreads();   // shared reuse barrier
    if (lid == 0) { sh_f[wid] = hs; sh_i[wid] = nc; }
    __syncthreads();

    if (t == 0) {
        float h = 0.0f; int n = 0;
#pragma unroll
        for (int w = 0; w < TPB / 32; w++) { h += sh_f[w]; n += sh_i[w]; }
        if (len > 0 && n > 0) {              // valid_obs = (len>0) & has_neg
            atomicAdd(&g_total, h / (float)n);
            atomicAdd(&g_count, 1.0f);
        }
        __threadfence();
        const unsigned d = atomicAdd(&g_done, 1u);
        if (d == gridDim.x - 1) {
            // Last CTA: all other CTAs' atomics are visible (their fence
            // preceded their done-increment).
            const float T = *((volatile float*)&g_total);
            const float C = *((volatile float*)&g_count);
            out[0] = (C > 0.0f) ? (T / fmaxf(C, 1.0f)) : 0.0f;
            // Reset for the next launch/replay.
            *((volatile float*)&g_total) = 0.0f;
            *((volatile float*)&g_count) = 0.0f;
            __threadfence();
            *((volatile unsigned int*)&g_done) = 0u;
        }
    }
}

extern "C" void kernel_launch(void* const* d_in, const int* in_sizes, int n_in,
                              void* d_out, int out_size)
{
    const float* scores = (const float*)d_in[0];
    const int*   lens   = (const int*)d_in[1];
    const int*   labels = (const int*)d_in[2];
    float* out = (float*)d_out;

    const int B = in_sizes[1];            // candidate_lengths element count
    const int L = in_sizes[0] / B;        // 2048

    hinge_row_kernel<<<B, TPB>>>(scores, lens, labels, L, out);
}

// round 5
// speedup vs baseline: 1.3473x; 1.3473x over previous
#include <cuda_runtime.h>
#include <cstdint>

#define MARGIN 0.1f
#define TPB 256
#define VPT 2           // float4 vectors per thread: TPB*VPT*4 = 2048 = L
#define EPT (VPT * 4)

// Global accumulators. Zero at module load; hinge_final_kernel resets them to
// zero after each launch, so every invocation (correctness call, capture call,
// each graph replay) observes identical initial state.
__device__ float g_total;
__device__ float g_count;

__global__ void __launch_bounds__(TPB) hinge_row_kernel(
    const float* __restrict__ scores,
    const int* __restrict__ lens,
    const int* __restrict__ labels,
    int L)
{
    const int row = blockIdx.x;
    const int len = lens[row];
    const size_t base = (size_t)row * (size_t)L;
    const float4* __restrict__ srow = (const float4*)(scores + base);
    const int4*   __restrict__ lrow = (const int4*)(labels + base);
    const int t = threadIdx.x;
    const int L4 = L >> 2;

    float s[EPT];
    bool isNeg[EPT];

    float pos_sum = 0.0f;
    int pos_cnt = 0;

#pragma unroll
    for (int k = 0; k < VPT; k++) {
        const int v = t + k * TPB;
        float4 sv = make_float4(0.f, 0.f, 0.f, 0.f);
        int4   lv = make_int4(-1, -1, -1, -1);
        if (v < L4) {
            sv = srow[v];
            lv = lrow[v];
        }
        const int j0 = v << 2;
        const float se[4] = { sv.x, sv.y, sv.z, sv.w };
        const int   le[4] = { lv.x, lv.y, lv.z, lv.w };
#pragma unroll
        for (int e = 0; e < 4; e++) {
            const int j = j0 + e;
            const bool valid = (j < L) && (j < len);
            const bool p = valid && (le[e] == 1);
            const bool n = valid && (le[e] == 0);
            s[k * 4 + e] = se[e];
            isNeg[k * 4 + e] = n;
            if (p) { pos_sum += se[e]; pos_cnt++; }
        }
    }

    // ---- block reduce pos_sum / pos_cnt ----
    __shared__ float sh_f[TPB / 32];
    __shared__ int   sh_i[TPB / 32];
    __shared__ float sh_chosen;

#pragma unroll
    for (int o = 16; o > 0; o >>= 1) {
        pos_sum += __shfl_down_sync(0xFFFFFFFFu, pos_sum, o);
        pos_cnt += __shfl_down_sync(0xFFFFFFFFu, pos_cnt, o);
    }
    const int wid = t >> 5, lid = t & 31;
    if (lid == 0) { sh_f[wid] = pos_sum; sh_i[wid] = pos_cnt; }
    __syncthreads();
    if (t == 0) {
        float ps = 0.0f; int pc = 0;
#pragma unroll
        for (int w = 0; w < TPB / 32; w++) { ps += sh_f[w]; pc += sh_i[w]; }
        sh_chosen = (pc > 0) ? ps : -MARGIN;
    }
    __syncthreads();
    const float chosen = sh_chosen;

    // ---- hinge over negatives, from register-resident scores ----
    float hs = 0.0f;
    int nc = 0;
#pragma unroll
    for (int k = 0; k < EPT; k++) {
        if (isNeg[k]) {
            hs += fmaxf(MARGIN + s[k] - chosen, 0.0f);
            nc++;
        }
    }
#pragma unroll
    for (int o = 16; o > 0; o >>= 1) {
        hs += __shfl_down_sync(0xFFFFFFFFu, hs, o);
        nc += __shfl_down_sync(0xFFFFFFFFu, nc, o);
    }
    __syncthreads();   // shared reuse barrier
    if (lid == 0) { sh_f[wid] = hs; sh_i[wid] = nc; }
    __syncthreads();
    if (t == 0) {
        float h = 0.0f; int n = 0;
#pragma unroll
        for (int w = 0; w < TPB / 32; w++) { h += sh_f[w]; n += sh_i[w]; }
        if (len > 0 && n > 0) {              // valid_obs = (len>0) & has_neg
            atomicAdd(&g_total, h / (float)n);
            atomicAdd(&g_count, 1.0f);
        }
    }
}

__global__ void hinge_final_kernel(float* __restrict__ out)
{
    const float T = g_total;
    const float C = g_count;
    out[0] = (C > 0.0f) ? (T / fmaxf(C, 1.0f)) : 0.0f;
    // Reset for the next launch / graph replay.
    g_total = 0.0f;
    g_count = 0.0f;
}

extern "C" void kernel_launch(void* const* d_in, const int* in_sizes, int n_in,
                              void* d_out, int out_size)
{
    const float* scores = (const float*)d_in[0];
    const int*   lens   = (const int*)d_in[1];
    const int*   labels = (const int*)d_in[2];
    float* out = (float*)d_out;

    const int B = in_sizes[1];            // candidate_lengths element count
    const int L = in_sizes[0] / B;        // 2048

    hinge_row_kernel<<<B, TPB>>>(scores, lens, labels, L);
    hinge_final_kernel<<<1, 1>>>(out);
}